// round 11
// baseline (speedup 1.0000x reference)
#include <cuda_runtime.h>
#include <math.h>

#define NSEQ 256
#define CDIM 128
#define NHEAD 4
#define DHEAD 32
#define NROWS (NSEQ * NSEQ)

// ---------------- scratch (device globals; no allocation allowed) ----------------
__device__ float g_qkv[(size_t)NROWS * 3 * CDIM];   // 96 MB
__device__ float g_attn[(size_t)NROWS * CDIM];      // 32 MB
__device__ float g_sums[NSEQ * CDIM];               // row/col prefix sums
__device__ float g_h1[NSEQ * 2 * CDIM];
__device__ float g_h2[NSEQ * CDIM];
__device__ float g_bias_row[NSEQ * NSEQ];           // dscale*dist with mask folded
__device__ float g_bias_col[NSEQ * NSEQ];

// ---------------- helpers ----------------
__device__ __forceinline__ float warp_sum(float v) {
#pragma unroll
    for (int o = 16; o; o >>= 1) v += __shfl_xor_sync(0xffffffffu, v, o);
    return v;
}
__device__ __forceinline__ float warp_max(float v) {
#pragma unroll
    for (int o = 16; o; o >>= 1) v = fmaxf(v, __shfl_xor_sync(0xffffffffu, v, o));
    return v;
}
__device__ __forceinline__ unsigned f2tf32(float f) {
    unsigned u;
    asm("cvt.rna.tf32.f32 %0, %1;" : "=r"(u) : "f"(f));
    return u;
}
// D += A*B  (m16n8k8 tf32, A row-major, B col-major(k,n))
__device__ __forceinline__ void mma_tf32(float d[4], const unsigned a[4], const unsigned b[2]) {
    asm volatile(
        "mma.sync.aligned.m16n8k8.row.col.f32.tf32.tf32.f32 "
        "{%0,%1,%2,%3}, {%4,%5,%6,%7}, {%8,%9}, {%0,%1,%2,%3};"
        : "+f"(d[0]), "+f"(d[1]), "+f"(d[2]), "+f"(d[3])
        : "r"(a[0]), "r"(a[1]), "r"(a[2]), "r"(a[3]), "r"(b[0]), "r"(b[1]));
}

#define AS_STR 20
#define BS_STR 136
#define CS_STR 136

// ---------------- mask detect + fused bias tables ----------------
__global__ void maskbias_kernel(const unsigned char* __restrict__ m,
                                const float* __restrict__ dist,
                                const float* __restrict__ rdsc,
                                const float* __restrict__ cdsc) {
    __shared__ int flag;
    int tid = threadIdx.x;
    if (tid == 0) flag = 0;
    __syncthreads();
    int local = 0;
    for (int idx = tid; idx < NSEQ * NSEQ; idx += blockDim.x)
        if ((idx & 3) && m[idx]) local = 1;
    if (local) atomicOr(&flag, 1);
    __syncthreads();
    int isBytes = flag;
    float rs = rdsc[0], cs = cdsc[0];
    for (int idx = tid; idx < NSEQ * NSEQ; idx += blockDim.x) {
        int t = (idx & 255) * 256 + (idx >> 8);
        unsigned char mb = isBytes ? m[idx] : m[4 * (size_t)idx];
        unsigned char mt = isBytes ? m[t] : m[4 * (size_t)t];
        float dv = dist[idx];
        g_bias_row[idx] = mb ? -1e30f : rs * dv;
        g_bias_col[idx] = mt ? -1e30f : cs * dv;
    }
}

// ---------------- prefix sums ----------------
__global__ void rowsum_kernel(const float* __restrict__ pair) {
    int i = blockIdx.x, c = threadIdx.x;
    const float* p = pair + (size_t)i * NSEQ * CDIM + c;
    float s = 0.f;
#pragma unroll 4
    for (int k = 0; k < i; k++) s += __ldg(&p[(size_t)k * CDIM]);
    g_sums[i * CDIM + c] = s;
}

__global__ void colsum_kernel(const float* __restrict__ pr) {
    int j = blockIdx.x, c = threadIdx.x;
    const float* p = pr + (size_t)j * CDIM + c;
    float s = 0.f;
#pragma unroll 4
    for (int k = 0; k < j; k++) s += __ldg(&p[(size_t)k * NSEQ * CDIM]);
    g_sums[j * CDIM + c] = s;
}

// ---------------- fused tri-update + LayerNorm (warp per (i,j) row) ----------------
__global__ __launch_bounds__(256)
void trimix_ln_kernel(float* __restrict__ out, const float* __restrict__ src,
                      const float* __restrict__ single,
                      const float* __restrict__ g, const float* __restrict__ b,
                      int mode) {
    int lane = threadIdx.x & 31, warp = threadIdx.x >> 5;
    int row = blockIdx.x * 8 + warp;
    int i = row >> 8, j = row & 255;
    const float* sA = single + (size_t)(mode == 0 ? j : i) * CDIM;
    const float* sB = g_sums + (size_t)(mode == 0 ? i : j) * CDIM;
    const float* xr = src + (size_t)row * CDIM;

    float v[4];
    float mean = 0.f;
#pragma unroll
    for (int q = 0; q < 4; q++) {
        int c = q * 32 + lane;
        v[q] = xr[c] + sA[c] + sB[c];
        mean += v[q];
    }
    mean = warp_sum(mean) * (1.0f / CDIM);
    float var = 0.f;
#pragma unroll
    for (int q = 0; q < 4; q++) { float d = v[q] - mean; var += d * d; }
    var = warp_sum(var) * (1.0f / CDIM);
    float inv = rsqrtf(var + 1e-5f);
    float* orow = out + (size_t)row * CDIM;
#pragma unroll
    for (int q = 0; q < 4; q++) {
        int c = q * 32 + lane;
        orow[c] = (v[q] - mean) * inv * g[c] + b[c];
    }
}

__global__ __launch_bounds__(256)
void residual_ln_kernel(float* __restrict__ out, const float* __restrict__ x,
                        const float* __restrict__ y,
                        const float* __restrict__ g, const float* __restrict__ b,
                        int nrows) {
    int lane = threadIdx.x & 31, warp = threadIdx.x >> 5;
    int row = blockIdx.x * 8 + warp;
    if (row >= nrows) return;
    const float* xr = x + (size_t)row * CDIM;
    const float* yr = y + (size_t)row * CDIM;
    float v[4];
    float mean = 0.f;
#pragma unroll
    for (int q = 0; q < 4; q++) {
        int c = q * 32 + lane;
        v[q] = xr[c] + yr[c];
        mean += v[q];
    }
    mean = warp_sum(mean) * (1.0f / CDIM);
    float var = 0.f;
#pragma unroll
    for (int q = 0; q < 4; q++) { float d = v[q] - mean; var += d * d; }
    var = warp_sum(var) * (1.0f / CDIM);
    float inv = rsqrtf(var + 1e-5f);
    float* orow = out + (size_t)row * CDIM;
#pragma unroll
    for (int q = 0; q < 4; q++) {
        int c = q * 32 + lane;
        orow[c] = (v[q] - mean) * inv * g[c] + b[c];
    }
}

// ---------------- TF32 tensor-core GEMM 128x128, double-buffered BK=16 ----------------
// C[M,N] = A[M,K] @ B[K,N] + bias (+relu). M%128==0, N%128==0, K%16==0.
// 8 warps: warp (wid&3)*32 m-rows x (wid>>2)*64 n-cols; 16 mma(m16n8k8) per k-step.
__global__ __launch_bounds__(256)
void gemm_tf32_kernel(const float* __restrict__ A, const float* __restrict__ B,
                      const float* __restrict__ bias, float* __restrict__ C,
                      int M, int N, int K, int relu) {
    __shared__ unsigned As[2][128 * AS_STR];   // [m][k], tf32 bits
    __shared__ unsigned Bs[2][16 * BS_STR];    // [k][n], tf32 bits
    int tid = threadIdx.x;
    int wid = tid >> 5, lane = tid & 31;
    int g = lane >> 2, t = lane & 3;
    int wm = (wid & 3) * 32, wn = (wid >> 2) * 64;
    int m0 = blockIdx.y * 128, n0 = blockIdx.x * 128;
    int arow = tid >> 1, acolg = (tid & 1) << 3;
    int brow = tid >> 4, bcol = (tid & 15) << 3;
    const float* Ap = A + (size_t)(m0 + arow) * K;

    float acc[2][8][4] = {};

    // stage tile 0
    {
        float4 a0 = *(const float4*)&Ap[acolg];
        float4 a1 = *(const float4*)&Ap[acolg + 4];
        unsigned* d = &As[0][arow * AS_STR + acolg];
        d[0] = f2tf32(a0.x); d[1] = f2tf32(a0.y); d[2] = f2tf32(a0.z); d[3] = f2tf32(a0.w);
        d[4] = f2tf32(a1.x); d[5] = f2tf32(a1.y); d[6] = f2tf32(a1.z); d[7] = f2tf32(a1.w);
        float4 b0 = *(const float4*)&B[(size_t)brow * N + n0 + bcol];
        float4 b1 = *(const float4*)&B[(size_t)brow * N + n0 + bcol + 4];
        unsigned* e = &Bs[0][brow * BS_STR + bcol];
        e[0] = f2tf32(b0.x); e[1] = f2tf32(b0.y); e[2] = f2tf32(b0.z); e[3] = f2tf32(b0.w);
        e[4] = f2tf32(b1.x); e[5] = f2tf32(b1.y); e[6] = f2tf32(b1.z); e[7] = f2tf32(b1.w);
    }
    __syncthreads();

    int buf = 0;
    for (int k0 = 16; k0 < K; k0 += 16) {
        float4 pa0 = *(const float4*)&Ap[k0 + acolg];
        float4 pa1 = *(const float4*)&Ap[k0 + acolg + 4];
        float4 pb0 = *(const float4*)&B[(size_t)(k0 + brow) * N + n0 + bcol];
        float4 pb1 = *(const float4*)&B[(size_t)(k0 + brow) * N + n0 + bcol + 4];
#pragma unroll
        for (int ks = 0; ks < 16; ks += 8) {
            unsigned af[2][4];
#pragma unroll
            for (int mt = 0; mt < 2; mt++) {
                int mb = wm + mt * 16;
                af[mt][0] = As[buf][(mb + g) * AS_STR + ks + t];
                af[mt][1] = As[buf][(mb + g + 8) * AS_STR + ks + t];
                af[mt][2] = As[buf][(mb + g) * AS_STR + ks + t + 4];
                af[mt][3] = As[buf][(mb + g + 8) * AS_STR + ks + t + 4];
            }
#pragma unroll
            for (int nt = 0; nt < 8; nt++) {
                unsigned bf[2];
                bf[0] = Bs[buf][(ks + t) * BS_STR + wn + nt * 8 + g];
                bf[1] = Bs[buf][(ks + t + 4) * BS_STR + wn + nt * 8 + g];
                mma_tf32(acc[0][nt], af[0], bf);
                mma_tf32(acc[1][nt], af[1], bf);
            }
        }
        int nb = buf ^ 1;
        unsigned* d = &As[nb][arow * AS_STR + acolg];
        d[0] = f2tf32(pa0.x); d[1] = f2tf32(pa0.y); d[2] = f2tf32(pa0.z); d[3] = f2tf32(pa0.w);
        d[4] = f2tf32(pa1.x); d[5] = f2tf32(pa1.y); d[6] = f2tf32(pa1.z); d[7] = f2tf32(pa1.w);
        unsigned* e = &Bs[nb][brow * BS_STR + bcol];
        e[0] = f2tf32(pb0.x); e[1] = f2tf32(pb0.y); e[2] = f2tf32(pb0.z); e[3] = f2tf32(pb0.w);
        e[4] = f2tf32(pb1.x); e[5] = f2tf32(pb1.y); e[6] = f2tf32(pb1.z); e[7] = f2tf32(pb1.w);
        __syncthreads();
        buf = nb;
    }
#pragma unroll
    for (int ks = 0; ks < 16; ks += 8) {
        unsigned af[2][4];
#pragma unroll
        for (int mt = 0; mt < 2; mt++) {
            int mb = wm + mt * 16;
            af[mt][0] = As[buf][(mb + g) * AS_STR + ks + t];
            af[mt][1] = As[buf][(mb + g + 8) * AS_STR + ks + t];
            af[mt][2] = As[buf][(mb + g) * AS_STR + ks + t + 4];
            af[mt][3] = As[buf][(mb + g + 8) * AS_STR + ks + t + 4];
        }
#pragma unroll
        for (int nt = 0; nt < 8; nt++) {
            unsigned bf[2];
            bf[0] = Bs[buf][(ks + t) * BS_STR + wn + nt * 8 + g];
            bf[1] = Bs[buf][(ks + t + 4) * BS_STR + wn + nt * 8 + g];
            mma_tf32(acc[0][nt], af[0], bf);
            mma_tf32(acc[1][nt], af[1], bf);
        }
    }

#pragma unroll
    for (int nt = 0; nt < 8; nt++) {
        int cb = n0 + wn + nt * 8 + 2 * t;
        float b0 = __ldg(&bias[cb]), b1 = __ldg(&bias[cb + 1]);
#pragma unroll
        for (int mt = 0; mt < 2; mt++) {
            int r = m0 + wm + mt * 16 + g;
            float2 lo = make_float2(acc[mt][nt][0] + b0, acc[mt][nt][1] + b1);
            float2 hi = make_float2(acc[mt][nt][2] + b0, acc[mt][nt][3] + b1);
            if (relu) {
                lo.x = fmaxf(lo.x, 0.f); lo.y = fmaxf(lo.y, 0.f);
                hi.x = fmaxf(hi.x, 0.f); hi.y = fmaxf(hi.y, 0.f);
            }
            *(float2*)&C[(size_t)r * N + cb] = lo;
            *(float2*)&C[(size_t)(r + 8) * N + cb] = hi;
        }
    }
}

// ---------------- TF32 out-proj + residual + LayerNorm (N=K=128), grid = M/128 ----------------
#define WOLN_SMEM_BYTES (128 * CS_STR * 4)   // 69632; staging (37888) overlaps
__global__ __launch_bounds__(256)
void gemm_wo_ln_tf32_kernel(const float* __restrict__ A, const float* __restrict__ B,
                            const float* __restrict__ bias, const float* __restrict__ xres,
                            const float* __restrict__ g_, const float* __restrict__ bb,
                            float* __restrict__ out) {
    extern __shared__ unsigned dynbuf[];
    unsigned (*As)[128 * AS_STR] = (unsigned(*)[128 * AS_STR])dynbuf;
    unsigned (*Bs)[16 * BS_STR] = (unsigned(*)[16 * BS_STR])(dynbuf + 2 * 128 * AS_STR);
    int tid = threadIdx.x;
    int wid = tid >> 5, lane = tid & 31;
    int g = lane >> 2, t = lane & 3;
    int wm = (wid & 3) * 32, wn = (wid >> 2) * 64;
    int m0 = blockIdx.x * 128;
    int arow = tid >> 1, acolg = (tid & 1) << 3;
    int brow = tid >> 4, bcol = (tid & 15) << 3;
    const float* Ap = A + (size_t)(m0 + arow) * 128;

    float acc[2][8][4] = {};
    {
        float4 a0 = *(const float4*)&Ap[acolg];
        float4 a1 = *(const float4*)&Ap[acolg + 4];
        unsigned* d = &As[0][arow * AS_STR + acolg];
        d[0] = f2tf32(a0.x); d[1] = f2tf32(a0.y); d[2] = f2tf32(a0.z); d[3] = f2tf32(a0.w);
        d[4] = f2tf32(a1.x); d[5] = f2tf32(a1.y); d[6] = f2tf32(a1.z); d[7] = f2tf32(a1.w);
        float4 b0 = *(const float4*)&B[(size_t)brow * 128 + bcol];
        float4 b1 = *(const float4*)&B[(size_t)brow * 128 + bcol + 4];
        unsigned* e = &Bs[0][brow * BS_STR + bcol];
        e[0] = f2tf32(b0.x); e[1] = f2tf32(b0.y); e[2] = f2tf32(b0.z); e[3] = f2tf32(b0.w);
        e[4] = f2tf32(b1.x); e[5] = f2tf32(b1.y); e[6] = f2tf32(b1.z); e[7] = f2tf32(b1.w);
    }
    __syncthreads();

    int buf = 0;
    for (int k0 = 16; k0 < 128; k0 += 16) {
        float4 pa0 = *(const float4*)&Ap[k0 + acolg];
        float4 pa1 = *(const float4*)&Ap[k0 + acolg + 4];
        float4 pb0 = *(const float4*)&B[(size_t)(k0 + brow) * 128 + bcol];
        float4 pb1 = *(const float4*)&B[(size_t)(k0 + brow) * 128 + bcol + 4];
#pragma unroll
        for (int ks = 0; ks < 16; ks += 8) {
            unsigned af[2][4];
#pragma unroll
            for (int mt = 0; mt < 2; mt++) {
                int mb = wm + mt * 16;
                af[mt][0] = As[buf][(mb + g) * AS_STR + ks + t];
                af[mt][1] = As[buf][(mb + g + 8) * AS_STR + ks + t];
                af[mt][2] = As[buf][(mb + g) * AS_STR + ks + t + 4];
                af[mt][3] = As[buf][(mb + g + 8) * AS_STR + ks + t + 4];
            }
#pragma unroll
            for (int nt = 0; nt < 8; nt++) {
                unsigned bf[2];
                bf[0] = Bs[buf][(ks + t) * BS_STR + wn + nt * 8 + g];
                bf[1] = Bs[buf][(ks + t + 4) * BS_STR + wn + nt * 8 + g];
                mma_tf32(acc[0][nt], af[0], bf);
                mma_tf32(acc[1][nt], af[1], bf);
            }
        }
        int nb = buf ^ 1;
        unsigned* d = &As[nb][arow * AS_STR + acolg];
        d[0] = f2tf32(pa0.x); d[1] = f2tf32(pa0.y); d[2] = f2tf32(pa0.z); d[3] = f2tf32(pa0.w);
        d[4] = f2tf32(pa1.x); d[5] = f2tf32(pa1.y); d[6] = f2tf32(pa1.z); d[7] = f2tf32(pa1.w);
        unsigned* e = &Bs[nb][brow * BS_STR + bcol];
        e[0] = f2tf32(pb0.x); e[1] = f2tf32(pb0.y); e[2] = f2tf32(pb0.z); e[3] = f2tf32(pb0.w);
        e[4] = f2tf32(pb1.x); e[5] = f2tf32(pb1.y); e[6] = f2tf32(pb1.z); e[7] = f2tf32(pb1.w);
        __syncthreads();
        buf = nb;
    }
#pragma unroll
    for (int ks = 0; ks < 16; ks += 8) {
        unsigned af[2][4];
#pragma unroll
        for (int mt = 0; mt < 2; mt++) {
            int mb = wm + mt * 16;
            af[mt][0] = As[buf][(mb + g) * AS_STR + ks + t];
            af[mt][1] = As[buf][(mb + g + 8) * AS_STR + ks + t];
            af[mt][2] = As[buf][(mb + g) * AS_STR + ks + t + 4];
            af[mt][3] = As[buf][(mb + g + 8) * AS_STR + ks + t + 4];
        }
#pragma unroll
        for (int nt = 0; nt < 8; nt++) {
            unsigned bf[2];
            bf[0] = Bs[buf][(ks + t) * BS_STR + wn + nt * 8 + g];
            bf[1] = Bs[buf][(ks + t + 4) * BS_STR + wn + nt * 8 + g];
            mma_tf32(acc[0][nt], af[0], bf);
            mma_tf32(acc[1][nt], af[1], bf);
        }
    }

    // ---- write C (+bias) to smem, then residual+LN per row ----
    __syncthreads();                 // staging buffers dead; reuse as Cs
    float* Cs = (float*)dynbuf;      // [128][CS_STR]
#pragma unroll
    for (int nt = 0; nt < 8; nt++) {
        int cb = wn + nt * 8 + 2 * t;
        float b0 = __ldg(&bias[cb]), b1 = __ldg(&bias[cb + 1]);
#pragma unroll
        for (int mt = 0; mt < 2; mt++) {
            int lr = wm + mt * 16 + g;
            *(float2*)&Cs[lr * CS_STR + cb] =
                make_float2(acc[mt][nt][0] + b0, acc[mt][nt][1] + b1);
            *(float2*)&Cs[(lr + 8) * CS_STR + cb] =
                make_float2(acc[mt][nt][2] + b0, acc[mt][nt][3] + b1);
        }
    }
    __syncthreads();

    float4 gg = *(const float4*)&g_[lane * 4];
    float4 be = *(const float4*)&bb[lane * 4];
    for (int rr = 0; rr < 16; rr++) {
        int lr = wid * 16 + rr;
        int row = m0 + lr;
        float4 cv = *(float4*)&Cs[lr * CS_STR + lane * 4];
        float4 xv = *(const float4*)&xres[(size_t)row * 128 + lane * 4];
        float v0 = cv.x + xv.x, v1 = cv.y + xv.y, v2 = cv.z + xv.z, v3 = cv.w + xv.w;
        float mean = warp_sum(v0 + v1 + v2 + v3) * (1.0f / 128.0f);
        float d0 = v0 - mean, d1 = v1 - mean, d2 = v2 - mean, d3 = v3 - mean;
        float var = warp_sum(d0 * d0 + d1 * d1 + d2 * d2 + d3 * d3) * (1.0f / 128.0f);
        float inv = rsqrtf(var + 1e-5f);
        float4 o;
        o.x = d0 * inv * gg.x + be.x;
        o.y = d1 * inv * gg.y + be.y;
        o.z = d2 * inv * gg.z + be.z;
        o.w = d3 * inv * gg.w + be.w;
        *(float4*)&out[(size_t)row * 128 + lane * 4] = o;
    }
}

// ---------------- tiled attention: block per (jt, h, i); V read from gmem (L2-hot) ----------------
// smem floats: Qs[32][68] | Ks[32][260] | S[64][256]  -> 107.5 KB => 2 blocks/SM
#define ATT_QS 0
#define ATT_KS 2176
#define ATT_S  (ATT_KS + 32 * 260)
#define ATT_FLOATS (ATT_S + 64 * 256)
#define ATT_SMEM_BYTES (ATT_FLOATS * 4)

__global__ __launch_bounds__(256)
void attn_tile_kernel(const float* __restrict__ qkv, const float* __restrict__ biasmat,
                      float* __restrict__ out) {
    extern __shared__ float sh[];
    float* Qs = sh + ATT_QS;   // Q^T [d][j]
    float* Ks = sh + ATT_KS;   // K^T [d][k] stride 260
    float* S  = sh + ATT_S;    // exp-weights [j][k]
    int jt = blockIdx.x, h = blockIdx.y, i = blockIdx.z;
    int tid = threadIdx.x, lane = tid & 31, w = tid >> 5;
    const float* base = qkv + (size_t)i * NSEQ * 384;

    for (int idx = tid; idx < 64 * 32; idx += 256) {
        int j = idx >> 5, d = idx & 31;
        Qs[d * 68 + j] = base[(size_t)(jt * 64 + j) * 384 + h * 32 + d];
    }
    for (int idx = tid; idx < 256 * 32; idx += 256) {
        int k = idx >> 5, d = idx & 31;
        Ks[d * 260 + k] = base[(size_t)k * 384 + 128 + h * 32 + d];
    }
    __syncthreads();

    const float scale = 0.17677669529663687f;  // 1/sqrt(32)

    // ---- QK^T: warp w rows w*8..+7; thread cols {lane*4..+3} U {128+lane*4..+3} ----
    float acc[8][8];
#pragma unroll
    for (int r = 0; r < 8; r++)
#pragma unroll
        for (int c = 0; c < 8; c++) acc[r][c] = 0.f;

#pragma unroll 4
    for (int d = 0; d < 32; d++) {
        float qr[8], kr[8];
        *(float4*)(qr)     = *(const float4*)&Qs[d * 68 + w * 8];
        *(float4*)(qr + 4) = *(const float4*)&Qs[d * 68 + w * 8 + 4];
        *(float4*)(kr)     = *(const float4*)&Ks[d * 260 + lane * 4];
        *(float4*)(kr + 4) = *(const float4*)&Ks[d * 260 + 128 + lane * 4];
#pragma unroll
        for (int r = 0; r < 8; r++)
#pragma unroll
            for (int c = 0; c < 8; c++)
                acc[r][c] += qr[r] * kr[c];
    }

    // ---- fused bias + softmax in registers; store unnormalized exp, keep 1/sum ----
    int jrow0 = jt * 64 + w * 8;
    float invs[8];
#pragma unroll
    for (int r = 0; r < 8; r++) {
        const float* bm = biasmat + (size_t)(jrow0 + r) * 256;
        float4 b0 = __ldg((const float4*)(bm + lane * 4));
        float4 b1 = __ldg((const float4*)(bm + 128 + lane * 4));
        float v[8];
        v[0] = fmaf(acc[r][0], scale, b0.x); v[1] = fmaf(acc[r][1], scale, b0.y);
        v[2] = fmaf(acc[r][2], scale, b0.z); v[3] = fmaf(acc[r][3], scale, b0.w);
        v[4] = fmaf(acc[r][4], scale, b1.x); v[5] = fmaf(acc[r][5], scale, b1.y);
        v[6] = fmaf(acc[r][6], scale, b1.z); v[7] = fmaf(acc[r][7], scale, b1.w);
        float mx = v[0];
#pragma unroll
        for (int q = 1; q < 8; q++) mx = fmaxf(mx, v[q]);
        mx = warp_max(mx);
        float sum = 0.f;
#pragma unroll
        for (int q = 0; q < 8; q++) { v[q] = __expf(v[q] - mx); sum += v[q]; }
        sum = warp_sum(sum);
        invs[r] = 1.0f / sum;
        *(float4*)&S[(w * 8 + r) * 256 + lane * 4]       = *(float4*)(v);
        *(float4*)&S[(w * 8 + r) * 256 + 128 + lane * 4] = *(float4*)(v + 4);
    }
    __syncwarp();

    // ---- AV: V straight from gmem (coalesced, L2-hot), broadcast S rows ----
    const float* vb = base + 256 + h * 32 + lane;
    float o[8] = {};
    for (int k0 = 0; k0 < 256; k0 += 4) {
        float v0 = __ldg(vb + (size_t)(k0 + 0) * 384);
        float v1 = __ldg(vb + (size_t)(k0 + 1) * 384);
        float v2 = __ldg(vb + (size_t)(k0 + 2) * 384);
        float v3 = __ldg(vb + (size_t)(k0 + 3) * 384);
#pragma unroll
        for (int r = 0; r < 8; r++) {
            float4 wv = *(const float4*)&S[(w * 8 + r) * 256 + k0];
            o[r] += wv.x * v0 + wv.y * v1 + wv.z * v2 + wv.w * v3;
        }
    }
#pragma unroll
    for (int r = 0; r < 8; r++)
        out[((size_t)i * NSEQ + jrow0 + r) * CDIM + h * 32 + lane] = o[r] * invs[r];
}

// ---------------- launch ----------------
extern "C" void kernel_launch(void* const* d_in, const int* in_sizes, int n_in,
                              void* d_out, int out_size) {
    const float* pair      = (const float*)d_in[0];
    const float* single    = (const float*)d_in[1];
    const unsigned char* mask = (const unsigned char*)d_in[2];
    const float* dist      = (const float*)d_in[3];
    const float* row_Wqkv  = (const float*)d_in[4];
    const float* row_bqkv  = (const float*)d_in[5];
    const float* row_Wo    = (const float*)d_in[6];
    const float* row_bo    = (const float*)d_in[7];
    const float* row_dsc   = (const float*)d_in[8];
    const float* col_Wqkv  = (const float*)d_in[9];
    const float* col_bqkv  = (const float*)d_in[10];
    const float* col_Wo    = (const float*)d_in[11];
    const float* col_bo    = (const float*)d_in[12];
    const float* col_dsc   = (const float*)d_in[13];
    const float* pnr_g     = (const float*)d_in[14];
    const float* pnr_b     = (const float*)d_in[15];
    const float* pnc_g     = (const float*)d_in[16];
    const float* pnc_b     = (const float*)d_in[17];
    const float* sn_g      = (const float*)d_in[18];
    const float* sn_b      = (const float*)d_in[19];
    const float* W1        = (const float*)d_in[20];
    const float* b1        = (const float*)d_in[21];
    const float* W2        = (const float*)d_in[22];
    const float* b2        = (const float*)d_in[23];

    float* pr = (float*)d_out;                               // [256,256,128]
    float* sr = pr + (size_t)NROWS * CDIM;                   // [256,128]

    float *qkv_p, *attn_p, *h1_p, *h2_p, *brow_p, *bcol_p;
    cudaGetSymbolAddress((void**)&qkv_p, g_qkv);
    cudaGetSymbolAddress((void**)&attn_p, g_attn);
    cudaGetSymbolAddress((void**)&h1_p, g_h1);
    cudaGetSymbolAddress((void**)&h2_p, g_h2);
    cudaGetSymbolAddress((void**)&brow_p, g_bias_row);
    cudaGetSymbolAddress((void**)&bcol_p, g_bias_col);

    cudaFuncSetAttribute(attn_tile_kernel, cudaFuncAttributeMaxDynamicSharedMemorySize,
                         ATT_SMEM_BYTES);
    cudaFuncSetAttribute(gemm_wo_ln_tf32_kernel, cudaFuncAttributeMaxDynamicSharedMemorySize,
                         WOLN_SMEM_BYTES);

    // mask detection + fused bias tables
    maskbias_kernel<<<1, 1024>>>(mask, dist, row_dsc, col_dsc);

    // ---- stage 1: pr = LN(pair + tri_update_out(pair, single)) ----
    rowsum_kernel<<<NSEQ, CDIM>>>(pair);
    trimix_ln_kernel<<<NROWS / 8, 256>>>(pr, pair, single, pnr_g, pnr_b, 0);

    // ---- stage 2: pr = LN(pr + row_attn(pr)) ----
    gemm_tf32_kernel<<<dim3(3, 512), 256>>>(pr, row_Wqkv, row_bqkv, qkv_p, NROWS, 384, 128, 0);
    attn_tile_kernel<<<dim3(4, NHEAD, NSEQ), 256, ATT_SMEM_BYTES>>>(qkv_p, brow_p, attn_p);
    gemm_wo_ln_tf32_kernel<<<512, 256, WOLN_SMEM_BYTES>>>(attn_p, row_Wo, row_bo, pr,
                                                          pnr_g, pnr_b, pr);

    // ---- stage 3: pr = LN(pr + tri_update_in(pr, single)) ----
    colsum_kernel<<<NSEQ, CDIM>>>(pr);
    trimix_ln_kernel<<<NROWS / 8, 256>>>(pr, pr, single, pnc_g, pnc_b, 1);

    // ---- stage 4: pr = LN(pr + col_attn(pr)) ----
    gemm_tf32_kernel<<<dim3(3, 512), 256>>>(pr, col_Wqkv, col_bqkv, qkv_p, NROWS, 384, 128, 0);
    attn_tile_kernel<<<dim3(4, NHEAD, NSEQ), 256, ATT_SMEM_BYTES>>>(qkv_p, bcol_p, attn_p);
    gemm_wo_ln_tf32_kernel<<<512, 256, WOLN_SMEM_BYTES>>>(attn_p, col_Wo, col_bo, pr,
                                                          pnc_g, pnc_b, pr);

    // ---- single-rep MLP + LN ----
    gemm_tf32_kernel<<<dim3(2, 2), 256>>>(single, W1, b1, h1_p, NSEQ, 256, 128, 1);
    gemm_tf32_kernel<<<dim3(1, 2), 256>>>(h1_p, W2, b2, h2_p, NSEQ, 128, 256, 1);
    residual_ln_kernel<<<NSEQ / 8, 256>>>(sr, single, h2_p, sn_g, sn_b, NSEQ);
}

// round 12
// speedup vs baseline: 1.1032x; 1.1032x over previous
#include <cuda_runtime.h>
#include <math.h>

#define NSEQ 256
#define CDIM 128
#define NHEAD 4
#define DHEAD 32
#define NROWS (NSEQ * NSEQ)

// ---------------- scratch (device globals; no allocation allowed) ----------------
__device__ float g_qkv[(size_t)NROWS * 3 * CDIM];   // 96 MB
__device__ float g_attn[(size_t)NROWS * CDIM];      // 32 MB
__device__ float g_sums[NSEQ * CDIM];               // row/col prefix sums
__device__ float g_h1[NSEQ * 2 * CDIM];
__device__ float g_h2[NSEQ * CDIM];
__device__ float g_bias_row[NSEQ * NSEQ];           // dscale*dist with mask folded
__device__ float g_bias_col[NSEQ * NSEQ];

// ---------------- helpers ----------------
__device__ __forceinline__ float warp_sum(float v) {
#pragma unroll
    for (int o = 16; o; o >>= 1) v += __shfl_xor_sync(0xffffffffu, v, o);
    return v;
}
__device__ __forceinline__ float warp_max(float v) {
#pragma unroll
    for (int o = 16; o; o >>= 1) v = fmaxf(v, __shfl_xor_sync(0xffffffffu, v, o));
    return v;
}
__device__ __forceinline__ float half16_sum(float v) {
#pragma unroll
    for (int o = 8; o; o >>= 1) v += __shfl_xor_sync(0xffffffffu, v, o);
    return v;
}
__device__ __forceinline__ unsigned f2tf32(float f) {
    unsigned u;
    asm("cvt.rna.tf32.f32 %0, %1;" : "=r"(u) : "f"(f));
    return u;
}
__device__ __forceinline__ void mma_tf32(float d[4], const unsigned a[4], const unsigned b[2]) {
    asm volatile(
        "mma.sync.aligned.m16n8k8.row.col.f32.tf32.tf32.f32 "
        "{%0,%1,%2,%3}, {%4,%5,%6,%7}, {%8,%9}, {%0,%1,%2,%3};"
        : "+f"(d[0]), "+f"(d[1]), "+f"(d[2]), "+f"(d[3])
        : "r"(a[0]), "r"(a[1]), "r"(a[2]), "r"(a[3]), "r"(b[0]), "r"(b[1]));
}

#define AS_STR 20
#define BS_STR 136

// ---------------- mask detect + fused bias tables ----------------
__global__ void maskbias_kernel(const unsigned char* __restrict__ m,
                                const float* __restrict__ dist,
                                const float* __restrict__ rdsc,
                                const float* __restrict__ cdsc) {
    __shared__ int flag;
    int tid = threadIdx.x;
    if (tid == 0) flag = 0;
    __syncthreads();
    int local = 0;
    for (int idx = tid; idx < NSEQ * NSEQ; idx += blockDim.x)
        if ((idx & 3) && m[idx]) local = 1;
    if (local) atomicOr(&flag, 1);
    __syncthreads();
    int isBytes = flag;
    float rs = rdsc[0], cs = cdsc[0];
    for (int idx = tid; idx < NSEQ * NSEQ; idx += blockDim.x) {
        int t = (idx & 255) * 256 + (idx >> 8);
        unsigned char mb = isBytes ? m[idx] : m[4 * (size_t)idx];
        unsigned char mt = isBytes ? m[t] : m[4 * (size_t)t];
        float dv = dist[idx];
        g_bias_row[idx] = mb ? -1e30f : rs * dv;
        g_bias_col[idx] = mt ? -1e30f : cs * dv;
    }
}

// ---------------- prefix sums ----------------
__global__ void rowsum_kernel(const float* __restrict__ pair) {
    int i = blockIdx.x, c = threadIdx.x;
    const float* p = pair + (size_t)i * NSEQ * CDIM + c;
    float s = 0.f;
#pragma unroll 4
    for (int k = 0; k < i; k++) s += __ldg(&p[(size_t)k * CDIM]);
    g_sums[i * CDIM + c] = s;
}

__global__ void colsum_kernel(const float* __restrict__ pr) {
    int j = blockIdx.x, c = threadIdx.x;
    const float* p = pr + (size_t)j * CDIM + c;
    float s = 0.f;
#pragma unroll 4
    for (int k = 0; k < j; k++) s += __ldg(&p[(size_t)k * NSEQ * CDIM]);
    g_sums[j * CDIM + c] = s;
}

// ---------------- fused tri-update + LayerNorm (warp per (i,j) row) ----------------
__global__ __launch_bounds__(256)
void trimix_ln_kernel(float* __restrict__ out, const float* __restrict__ src,
                      const float* __restrict__ single,
                      const float* __restrict__ g, const float* __restrict__ b,
                      int mode) {
    int lane = threadIdx.x & 31, warp = threadIdx.x >> 5;
    int row = blockIdx.x * 8 + warp;
    int i = row >> 8, j = row & 255;
    const float* sA = single + (size_t)(mode == 0 ? j : i) * CDIM;
    const float* sB = g_sums + (size_t)(mode == 0 ? i : j) * CDIM;
    const float* xr = src + (size_t)row * CDIM;

    float v[4];
    float mean = 0.f;
#pragma unroll
    for (int q = 0; q < 4; q++) {
        int c = q * 32 + lane;
        v[q] = xr[c] + sA[c] + sB[c];
        mean += v[q];
    }
    mean = warp_sum(mean) * (1.0f / CDIM);
    float var = 0.f;
#pragma unroll
    for (int q = 0; q < 4; q++) { float d = v[q] - mean; var += d * d; }
    var = warp_sum(var) * (1.0f / CDIM);
    float inv = rsqrtf(var + 1e-5f);
    float* orow = out + (size_t)row * CDIM;
#pragma unroll
    for (int q = 0; q < 4; q++) {
        int c = q * 32 + lane;
        orow[c] = (v[q] - mean) * inv * g[c] + b[c];
    }
}

__global__ __launch_bounds__(256)
void residual_ln_kernel(float* __restrict__ out, const float* __restrict__ x,
                        const float* __restrict__ y,
                        const float* __restrict__ g, const float* __restrict__ b,
                        int nrows) {
    int lane = threadIdx.x & 31, warp = threadIdx.x >> 5;
    int row = blockIdx.x * 8 + warp;
    if (row >= nrows) return;
    const float* xr = x + (size_t)row * CDIM;
    const float* yr = y + (size_t)row * CDIM;
    float v[4];
    float mean = 0.f;
#pragma unroll
    for (int q = 0; q < 4; q++) {
        int c = q * 32 + lane;
        v[q] = xr[c] + yr[c];
        mean += v[q];
    }
    mean = warp_sum(mean) * (1.0f / CDIM);
    float var = 0.f;
#pragma unroll
    for (int q = 0; q < 4; q++) { float d = v[q] - mean; var += d * d; }
    var = warp_sum(var) * (1.0f / CDIM);
    float inv = rsqrtf(var + 1e-5f);
    float* orow = out + (size_t)row * CDIM;
#pragma unroll
    for (int q = 0; q < 4; q++) {
        int c = q * 32 + lane;
        orow[c] = (v[q] - mean) * inv * g[c] + b[c];
    }
}

// ---------------- TF32 tensor-core GEMM 128x128, double-buffered BK=16 (validated R11) ----------------
__global__ __launch_bounds__(256)
void gemm_tf32_kernel(const float* __restrict__ A, const float* __restrict__ B,
                      const float* __restrict__ bias, float* __restrict__ C,
                      int M, int N, int K, int relu) {
    __shared__ unsigned As[2][128 * AS_STR];
    __shared__ unsigned Bs[2][16 * BS_STR];
    int tid = threadIdx.x;
    int wid = tid >> 5, lane = tid & 31;
    int g = lane >> 2, t = lane & 3;
    int wm = (wid & 3) * 32, wn = (wid >> 2) * 64;
    int m0 = blockIdx.y * 128, n0 = blockIdx.x * 128;
    int arow = tid >> 1, acolg = (tid & 1) << 3;
    int brow = tid >> 4, bcol = (tid & 15) << 3;
    const float* Ap = A + (size_t)(m0 + arow) * K;

    float acc[2][8][4] = {};

    {
        float4 a0 = *(const float4*)&Ap[acolg];
        float4 a1 = *(const float4*)&Ap[acolg + 4];
        unsigned* d = &As[0][arow * AS_STR + acolg];
        d[0] = f2tf32(a0.x); d[1] = f2tf32(a0.y); d[2] = f2tf32(a0.z); d[3] = f2tf32(a0.w);
        d[4] = f2tf32(a1.x); d[5] = f2tf32(a1.y); d[6] = f2tf32(a1.z); d[7] = f2tf32(a1.w);
        float4 b0 = *(const float4*)&B[(size_t)brow * N + n0 + bcol];
        float4 b1 = *(const float4*)&B[(size_t)brow * N + n0 + bcol + 4];
        unsigned* e = &Bs[0][brow * BS_STR + bcol];
        e[0] = f2tf32(b0.x); e[1] = f2tf32(b0.y); e[2] = f2tf32(b0.z); e[3] = f2tf32(b0.w);
        e[4] = f2tf32(b1.x); e[5] = f2tf32(b1.y); e[6] = f2tf32(b1.z); e[7] = f2tf32(b1.w);
    }
    __syncthreads();

    int buf = 0;
    for (int k0 = 16; k0 < K; k0 += 16) {
        float4 pa0 = *(const float4*)&Ap[k0 + acolg];
        float4 pa1 = *(const float4*)&Ap[k0 + acolg + 4];
        float4 pb0 = *(const float4*)&B[(size_t)(k0 + brow) * N + n0 + bcol];
        float4 pb1 = *(const float4*)&B[(size_t)(k0 + brow) * N + n0 + bcol + 4];
#pragma unroll
        for (int ks = 0; ks < 16; ks += 8) {
            unsigned af[2][4];
#pragma unroll
            for (int mt = 0; mt < 2; mt++) {
                int mb = wm + mt * 16;
                af[mt][0] = As[buf][(mb + g) * AS_STR + ks + t];
                af[mt][1] = As[buf][(mb + g + 8) * AS_STR + ks + t];
                af[mt][2] = As[buf][(mb + g) * AS_STR + ks + t + 4];
                af[mt][3] = As[buf][(mb + g + 8) * AS_STR + ks + t + 4];
            }
#pragma unroll
            for (int nt = 0; nt < 8; nt++) {
                unsigned bf[2];
                bf[0] = Bs[buf][(ks + t) * BS_STR + wn + nt * 8 + g];
                bf[1] = Bs[buf][(ks + t + 4) * BS_STR + wn + nt * 8 + g];
                mma_tf32(acc[0][nt], af[0], bf);
                mma_tf32(acc[1][nt], af[1], bf);
            }
        }
        int nb = buf ^ 1;
        unsigned* d = &As[nb][arow * AS_STR + acolg];
        d[0] = f2tf32(pa0.x); d[1] = f2tf32(pa0.y); d[2] = f2tf32(pa0.z); d[3] = f2tf32(pa0.w);
        d[4] = f2tf32(pa1.x); d[5] = f2tf32(pa1.y); d[6] = f2tf32(pa1.z); d[7] = f2tf32(pa1.w);
        unsigned* e = &Bs[nb][brow * BS_STR + bcol];
        e[0] = f2tf32(pb0.x); e[1] = f2tf32(pb0.y); e[2] = f2tf32(pb0.z); e[3] = f2tf32(pb0.w);
        e[4] = f2tf32(pb1.x); e[5] = f2tf32(pb1.y); e[6] = f2tf32(pb1.z); e[7] = f2tf32(pb1.w);
        __syncthreads();
        buf = nb;
    }
#pragma unroll
    for (int ks = 0; ks < 16; ks += 8) {
        unsigned af[2][4];
#pragma unroll
        for (int mt = 0; mt < 2; mt++) {
            int mb = wm + mt * 16;
            af[mt][0] = As[buf][(mb + g) * AS_STR + ks + t];
            af[mt][1] = As[buf][(mb + g + 8) * AS_STR + ks + t];
            af[mt][2] = As[buf][(mb + g) * AS_STR + ks + t + 4];
            af[mt][3] = As[buf][(mb + g + 8) * AS_STR + ks + t + 4];
        }
#pragma unroll
        for (int nt = 0; nt < 8; nt++) {
            unsigned bf[2];
            bf[0] = Bs[buf][(ks + t) * BS_STR + wn + nt * 8 + g];
            bf[1] = Bs[buf][(ks + t + 4) * BS_STR + wn + nt * 8 + g];
            mma_tf32(acc[0][nt], af[0], bf);
            mma_tf32(acc[1][nt], af[1], bf);
        }
    }

#pragma unroll
    for (int nt = 0; nt < 8; nt++) {
        int cb = n0 + wn + nt * 8 + 2 * t;
        float b0 = __ldg(&bias[cb]), b1 = __ldg(&bias[cb + 1]);
#pragma unroll
        for (int mt = 0; mt < 2; mt++) {
            int r = m0 + wm + mt * 16 + g;
            float2 lo = make_float2(acc[mt][nt][0] + b0, acc[mt][nt][1] + b1);
            float2 hi = make_float2(acc[mt][nt][2] + b0, acc[mt][nt][3] + b1);
            if (relu) {
                lo.x = fmaxf(lo.x, 0.f); lo.y = fmaxf(lo.y, 0.f);
                hi.x = fmaxf(hi.x, 0.f); hi.y = fmaxf(hi.y, 0.f);
            }
            *(float2*)&C[(size_t)r * N + cb] = lo;
            *(float2*)&C[(size_t)(r + 8) * N + cb] = hi;
        }
    }
}

// ---------------- FMA SGEMM 128x128x16 (validated R6-R9; used for MLP) ----------------
__global__ __launch_bounds__(256)
void gemm128_kernel(const float* __restrict__ A, const float* __restrict__ B,
                    const float* __restrict__ bias, float* __restrict__ C,
                    int M, int N, int K, int relu) {
    __shared__ float As[2][16][128];
    __shared__ float Bs[2][16][132];
    int tid = threadIdx.x;
    int m0 = blockIdx.y * 128, n0 = blockIdx.x * 128;
    int tx = tid & 15, ty = tid >> 4;
    int arow = tid >> 1, acolg = (tid & 1) << 3;
    int brow = tid >> 5, bcol = (tid & 31) << 2;
    const float* Aptr = A + (size_t)(m0 + arow) * K;

    {
        float4 a0 = *(const float4*)&Aptr[acolg];
        float4 a1 = *(const float4*)&Aptr[acolg + 4];
        As[0][acolg + 0][arow] = a0.x; As[0][acolg + 1][arow] = a0.y;
        As[0][acolg + 2][arow] = a0.z; As[0][acolg + 3][arow] = a0.w;
        As[0][acolg + 4][arow] = a1.x; As[0][acolg + 5][arow] = a1.y;
        As[0][acolg + 6][arow] = a1.z; As[0][acolg + 7][arow] = a1.w;
        *(float4*)&Bs[0][brow][bcol]     = *(const float4*)&B[(size_t)brow * N + n0 + bcol];
        *(float4*)&Bs[0][brow + 8][bcol] = *(const float4*)&B[(size_t)(brow + 8) * N + n0 + bcol];
    }
    __syncthreads();

    float acc[8][8] = {};
    int buf = 0;
    for (int k0 = 16; k0 < K; k0 += 16) {
        float4 na0 = *(const float4*)&Aptr[k0 + acolg];
        float4 na1 = *(const float4*)&Aptr[k0 + acolg + 4];
        float4 nb0 = *(const float4*)&B[(size_t)(k0 + brow) * N + n0 + bcol];
        float4 nb1 = *(const float4*)&B[(size_t)(k0 + brow + 8) * N + n0 + bcol];
#pragma unroll
        for (int kk = 0; kk < 16; kk++) {
            float a[8], b[8];
            *(float4*)(a)     = *(const float4*)&As[buf][kk][ty * 8];
            *(float4*)(a + 4) = *(const float4*)&As[buf][kk][ty * 8 + 4];
            *(float4*)(b)     = *(const float4*)&Bs[buf][kk][tx * 8];
            *(float4*)(b + 4) = *(const float4*)&Bs[buf][kk][tx * 8 + 4];
#pragma unroll
            for (int i2 = 0; i2 < 8; i2++)
#pragma unroll
                for (int j2 = 0; j2 < 8; j2++)
                    acc[i2][j2] += a[i2] * b[j2];
        }
        int nb = buf ^ 1;
        As[nb][acolg + 0][arow] = na0.x; As[nb][acolg + 1][arow] = na0.y;
        As[nb][acolg + 2][arow] = na0.z; As[nb][acolg + 3][arow] = na0.w;
        As[nb][acolg + 4][arow] = na1.x; As[nb][acolg + 5][arow] = na1.y;
        As[nb][acolg + 6][arow] = na1.z; As[nb][acolg + 7][arow] = na1.w;
        *(float4*)&Bs[nb][brow][bcol]     = nb0;
        *(float4*)&Bs[nb][brow + 8][bcol] = nb1;
        __syncthreads();
        buf = nb;
    }
#pragma unroll
    for (int kk = 0; kk < 16; kk++) {
        float a[8], b[8];
        *(float4*)(a)     = *(const float4*)&As[buf][kk][ty * 8];
        *(float4*)(a + 4) = *(const float4*)&As[buf][kk][ty * 8 + 4];
        *(float4*)(b)     = *(const float4*)&Bs[buf][kk][tx * 8];
        *(float4*)(b + 4) = *(const float4*)&Bs[buf][kk][tx * 8 + 4];
#pragma unroll
        for (int i2 = 0; i2 < 8; i2++)
#pragma unroll
            for (int j2 = 0; j2 < 8; j2++)
                acc[i2][j2] += a[i2] * b[j2];
    }

    float4 bi0 = *(const float4*)&bias[n0 + tx * 8];
    float4 bi1 = *(const float4*)&bias[n0 + tx * 8 + 4];
#pragma unroll
    for (int r = 0; r < 8; r++) {
        float* crow = C + (size_t)(m0 + ty * 8 + r) * N + n0 + tx * 8;
        float4 o0 = make_float4(acc[r][0] + bi0.x, acc[r][1] + bi0.y,
                                acc[r][2] + bi0.z, acc[r][3] + bi0.w);
        float4 o1 = make_float4(acc[r][4] + bi1.x, acc[r][5] + bi1.y,
                                acc[r][6] + bi1.z, acc[r][7] + bi1.w);
        if (relu) {
            o0.x = fmaxf(o0.x, 0.f); o0.y = fmaxf(o0.y, 0.f);
            o0.z = fmaxf(o0.z, 0.f); o0.w = fmaxf(o0.w, 0.f);
            o1.x = fmaxf(o1.x, 0.f); o1.y = fmaxf(o1.y, 0.f);
            o1.z = fmaxf(o1.z, 0.f); o1.w = fmaxf(o1.w, 0.f);
        }
        *(float4*)crow = o0;
        *(float4*)(crow + 4) = o1;
    }
}

// ---------------- FMA out-proj + residual + LayerNorm (validated R6-R9) ----------------
__global__ __launch_bounds__(256)
void gemm_wo_ln_kernel(const float* __restrict__ A, const float* __restrict__ B,
                       const float* __restrict__ bias, const float* __restrict__ xres,
                       const float* __restrict__ g, const float* __restrict__ bb,
                       float* __restrict__ out) {
    __shared__ float As[2][16][128];
    __shared__ float Bs[2][16][132];
    int tid = threadIdx.x;
    int m0 = blockIdx.x * 128;
    int tx = tid & 15, ty = tid >> 4;
    int arow = tid >> 1, acolg = (tid & 1) << 3;
    int brow = tid >> 5, bcol = (tid & 31) << 2;
    const float* Aptr = A + (size_t)(m0 + arow) * 128;

    {
        float4 a0 = *(const float4*)&Aptr[acolg];
        float4 a1 = *(const float4*)&Aptr[acolg + 4];
        As[0][acolg + 0][arow] = a0.x; As[0][acolg + 1][arow] = a0.y;
        As[0][acolg + 2][arow] = a0.z; As[0][acolg + 3][arow] = a0.w;
        As[0][acolg + 4][arow] = a1.x; As[0][acolg + 5][arow] = a1.y;
        As[0][acolg + 6][arow] = a1.z; As[0][acolg + 7][arow] = a1.w;
        *(float4*)&Bs[0][brow][bcol]     = *(const float4*)&B[(size_t)brow * 128 + bcol];
        *(float4*)&Bs[0][brow + 8][bcol] = *(const float4*)&B[(size_t)(brow + 8) * 128 + bcol];
    }
    __syncthreads();

    float acc[8][8] = {};
    int buf = 0;
    for (int k0 = 16; k0 < 128; k0 += 16) {
        float4 na0 = *(const float4*)&Aptr[k0 + acolg];
        float4 na1 = *(const float4*)&Aptr[k0 + acolg + 4];
        float4 nb0 = *(const float4*)&B[(size_t)(k0 + brow) * 128 + bcol];
        float4 nb1 = *(const float4*)&B[(size_t)(k0 + brow + 8) * 128 + bcol];
#pragma unroll
        for (int kk = 0; kk < 16; kk++) {
            float a[8], b[8];
            *(float4*)(a)     = *(const float4*)&As[buf][kk][ty * 8];
            *(float4*)(a + 4) = *(const float4*)&As[buf][kk][ty * 8 + 4];
            *(float4*)(b)     = *(const float4*)&Bs[buf][kk][tx * 8];
            *(float4*)(b + 4) = *(const float4*)&Bs[buf][kk][tx * 8 + 4];
#pragma unroll
            for (int i2 = 0; i2 < 8; i2++)
#pragma unroll
                for (int j2 = 0; j2 < 8; j2++)
                    acc[i2][j2] += a[i2] * b[j2];
        }
        int nb = buf ^ 1;
        As[nb][acolg + 0][arow] = na0.x; As[nb][acolg + 1][arow] = na0.y;
        As[nb][acolg + 2][arow] = na0.z; As[nb][acolg + 3][arow] = na0.w;
        As[nb][acolg + 4][arow] = na1.x; As[nb][acolg + 5][arow] = na1.y;
        As[nb][acolg + 6][arow] = na1.z; As[nb][acolg + 7][arow] = na1.w;
        *(float4*)&Bs[nb][brow][bcol]     = nb0;
        *(float4*)&Bs[nb][brow + 8][bcol] = nb1;
        __syncthreads();
        buf = nb;
    }
#pragma unroll
    for (int kk = 0; kk < 16; kk++) {
        float a[8], b[8];
        *(float4*)(a)     = *(const float4*)&As[buf][kk][ty * 8];
        *(float4*)(a + 4) = *(const float4*)&As[buf][kk][ty * 8 + 4];
        *(float4*)(b)     = *(const float4*)&Bs[buf][kk][tx * 8];
        *(float4*)(b + 4) = *(const float4*)&Bs[buf][kk][tx * 8 + 4];
#pragma unroll
        for (int i2 = 0; i2 < 8; i2++)
#pragma unroll
            for (int j2 = 0; j2 < 8; j2++)
                acc[i2][j2] += a[i2] * b[j2];
    }

    float4 bi0 = *(const float4*)&bias[tx * 8];
    float4 bi1 = *(const float4*)&bias[tx * 8 + 4];
    float4 g0  = *(const float4*)&g[tx * 8];
    float4 g1  = *(const float4*)&g[tx * 8 + 4];
    float4 be0 = *(const float4*)&bb[tx * 8];
    float4 be1 = *(const float4*)&bb[tx * 8 + 4];
#pragma unroll
    for (int r = 0; r < 8; r++) {
        int row = m0 + ty * 8 + r;
        const float* xr = xres + (size_t)row * 128 + tx * 8;
        float4 x0 = *(const float4*)xr;
        float4 x1 = *(const float4*)(xr + 4);
        float v[8];
        v[0] = acc[r][0] + bi0.x + x0.x; v[1] = acc[r][1] + bi0.y + x0.y;
        v[2] = acc[r][2] + bi0.z + x0.z; v[3] = acc[r][3] + bi0.w + x0.w;
        v[4] = acc[r][4] + bi1.x + x1.x; v[5] = acc[r][5] + bi1.y + x1.y;
        v[6] = acc[r][6] + bi1.z + x1.z; v[7] = acc[r][7] + bi1.w + x1.w;
        float s = 0.f;
#pragma unroll
        for (int q = 0; q < 8; q++) s += v[q];
        s = half16_sum(s);
        float mean = s * (1.0f / 128.0f);
        float d2 = 0.f;
#pragma unroll
        for (int q = 0; q < 8; q++) { float d = v[q] - mean; d2 += d * d; }
        d2 = half16_sum(d2);
        float inv = rsqrtf(d2 * (1.0f / 128.0f) + 1e-5f);
        float* orow = out + (size_t)row * 128 + tx * 8;
        float4 o0, o1;
        o0.x = (v[0] - mean) * inv * g0.x + be0.x;
        o0.y = (v[1] - mean) * inv * g0.y + be0.y;
        o0.z = (v[2] - mean) * inv * g0.z + be0.z;
        o0.w = (v[3] - mean) * inv * g0.w + be0.w;
        o1.x = (v[4] - mean) * inv * g1.x + be1.x;
        o1.y = (v[5] - mean) * inv * g1.y + be1.y;
        o1.z = (v[6] - mean) * inv * g1.z + be1.z;
        o1.w = (v[7] - mean) * inv * g1.w + be1.w;
        *(float4*)orow = o0;
        *(float4*)(orow + 4) = o1;
    }
}

// ---------------- tiled attention (validated R9): block per (jt, h, i), smem-staged V ----------------
#define ATT_QS 0
#define ATT_KS 2176
#define ATT_VS (ATT_KS + 32 * 260)
#define ATT_S  (ATT_VS + 256 * 33)
#define ATT_FLOATS (ATT_S + 64 * 256)
#define ATT_SMEM_BYTES (ATT_FLOATS * 4)

__global__ __launch_bounds__(256)
void attn_tile_kernel(const float* __restrict__ qkv, const float* __restrict__ biasmat,
                      float* __restrict__ out) {
    extern __shared__ float sh[];
    float* Qs = sh + ATT_QS;   // Q^T [d][j]
    float* Ks = sh + ATT_KS;   // K^T [d][k] stride 260
    float* Vs = sh + ATT_VS;   // V  [k][d] stride 33
    float* S  = sh + ATT_S;    // exp-weights [j][k]
    int jt = blockIdx.x, h = blockIdx.y, i = blockIdx.z;
    int tid = threadIdx.x, lane = tid & 31, w = tid >> 5;
    const float* base = qkv + (size_t)i * NSEQ * 384;

    for (int idx = tid; idx < 64 * 32; idx += 256) {
        int j = idx >> 5, d = idx & 31;
        Qs[d * 68 + j] = base[(size_t)(jt * 64 + j) * 384 + h * 32 + d];
    }
    for (int idx = tid; idx < 256 * 32; idx += 256) {
        int k = idx >> 5, d = idx & 31;
        Ks[d * 260 + k] = base[(size_t)k * 384 + 128 + h * 32 + d];
        Vs[k * 33 + d]  = base[(size_t)k * 384 + 256 + h * 32 + d];
    }
    __syncthreads();

    const float scale = 0.17677669529663687f;  // 1/sqrt(32)

    float acc[8][8];
#pragma unroll
    for (int r = 0; r < 8; r++)
#pragma unroll
        for (int c = 0; c < 8; c++) acc[r][c] = 0.f;

#pragma unroll 4
    for (int d = 0; d < 32; d++) {
        float qr[8], kr[8];
        *(float4*)(qr)     = *(const float4*)&Qs[d * 68 + w * 8];
        *(float4*)(qr + 4) = *(const float4*)&Qs[d * 68 + w * 8 + 4];
        *(float4*)(kr)     = *(const float4*)&Ks[d * 260 + lane * 4];
        *(float4*)(kr + 4) = *(const float4*)&Ks[d * 260 + 128 + lane * 4];
#pragma unroll
        for (int r = 0; r < 8; r++)
#pragma unroll
            for (int c = 0; c < 8; c++)
                acc[r][c] += qr[r] * kr[c];
    }

    int jrow0 = jt * 64 + w * 8;
    float invs[8];
#pragma unroll
    for (int r = 0; r < 8; r++) {
        const float* bm = biasmat + (size_t)(jrow0 + r) * 256;
        float4 b0 = __ldg((const float4*)(bm + lane * 4));
        float4 b1 = __ldg((const float4*)(bm + 128 + lane * 4));
        float v[8];
        v[0] = fmaf(acc[r][0], scale, b0.x); v[1] = fmaf(acc[r][1], scale, b0.y);
        v[2] = fmaf(acc[r][2], scale, b0.z); v[3] = fmaf(acc[r][3], scale, b0.w);
        v[4] = fmaf(acc[r][4], scale, b1.x); v[5] = fmaf(acc[r][5], scale, b1.y);
        v[6] = fmaf(acc[r][6], scale, b1.z); v[7] = fmaf(acc[r][7], scale, b1.w);
        float mx = v[0];
#pragma unroll
        for (int q = 1; q < 8; q++) mx = fmaxf(mx, v[q]);
        mx = warp_max(mx);
        float sum = 0.f;
#pragma unroll
        for (int q = 0; q < 8; q++) { v[q] = __expf(v[q] - mx); sum += v[q]; }
        sum = warp_sum(sum);
        invs[r] = 1.0f / sum;
        *(float4*)&S[(w * 8 + r) * 256 + lane * 4]       = *(float4*)(v);
        *(float4*)&S[(w * 8 + r) * 256 + 128 + lane * 4] = *(float4*)(v + 4);
    }
    __syncwarp();

    float o[8] = {};
    for (int k0 = 0; k0 < 256; k0 += 4) {
        float v0 = Vs[(k0 + 0) * 33 + lane];
        float v1 = Vs[(k0 + 1) * 33 + lane];
        float v2 = Vs[(k0 + 2) * 33 + lane];
        float v3 = Vs[(k0 + 3) * 33 + lane];
#pragma unroll
        for (int r = 0; r < 8; r++) {
            float4 wv = *(const float4*)&S[(w * 8 + r) * 256 + k0];
            o[r] += wv.x * v0 + wv.y * v1 + wv.z * v2 + wv.w * v3;
        }
    }
#pragma unroll
    for (int r = 0; r < 8; r++)
        out[((size_t)i * NSEQ + jrow0 + r) * CDIM + h * 32 + lane] = o[r] * invs[r];
}

// ---------------- launch ----------------
extern "C" void kernel_launch(void* const* d_in, const int* in_sizes, int n_in,
                              void* d_out, int out_size) {
    const float* pair      = (const float*)d_in[0];
    const float* single    = (const float*)d_in[1];
    const unsigned char* mask = (const unsigned char*)d_in[2];
    const float* dist      = (const float*)d_in[3];
    const float* row_Wqkv  = (const float*)d_in[4];
    const float* row_bqkv  = (const float*)d_in[5];
    const float* row_Wo    = (const float*)d_in[6];
    const float* row_bo    = (const float*)d_in[7];
    const float* row_dsc   = (const float*)d_in[8];
    const float* col_Wqkv  = (const float*)d_in[9];
    const float* col_bqkv  = (const float*)d_in[10];
    const float* col_Wo    = (const float*)d_in[11];
    const float* col_bo    = (const float*)d_in[12];
    const float* col_dsc   = (const float*)d_in[13];
    const float* pnr_g     = (const float*)d_in[14];
    const float* pnr_b     = (const float*)d_in[15];
    const float* pnc_g     = (const float*)d_in[16];
    const float* pnc_b     = (const float*)d_in[17];
    const float* sn_g      = (const float*)d_in[18];
    const float* sn_b      = (const float*)d_in[19];
    const float* W1        = (const float*)d_in[20];
    const float* b1        = (const float*)d_in[21];
    const float* W2        = (const float*)d_in[22];
    const float* b2        = (const float*)d_in[23];

    float* pr = (float*)d_out;                               // [256,256,128]
    float* sr = pr + (size_t)NROWS * CDIM;                   // [256,128]

    float *qkv_p, *attn_p, *h1_p, *h2_p, *brow_p, *bcol_p;
    cudaGetSymbolAddress((void**)&qkv_p, g_qkv);
    cudaGetSymbolAddress((void**)&attn_p, g_attn);
    cudaGetSymbolAddress((void**)&h1_p, g_h1);
    cudaGetSymbolAddress((void**)&h2_p, g_h2);
    cudaGetSymbolAddress((void**)&brow_p, g_bias_row);
    cudaGetSymbolAddress((void**)&bcol_p, g_bias_col);

    cudaFuncSetAttribute(attn_tile_kernel, cudaFuncAttributeMaxDynamicSharedMemorySize,
                         ATT_SMEM_BYTES);

    // mask detection + fused bias tables
    maskbias_kernel<<<1, 1024>>>(mask, dist, row_dsc, col_dsc);

    // ---- stage 1: pr = LN(pair + tri_update_out(pair, single)) ----
    rowsum_kernel<<<NSEQ, CDIM>>>(pair);
    trimix_ln_kernel<<<NROWS / 8, 256>>>(pr, pair, single, pnr_g, pnr_b, 0);

    // ---- stage 2: pr = LN(pr + row_attn(pr)) ----
    gemm_tf32_kernel<<<dim3(3, 512), 256>>>(pr, row_Wqkv, row_bqkv, qkv_p, NROWS, 384, 128, 0);
    attn_tile_kernel<<<dim3(4, NHEAD, NSEQ), 256, ATT_SMEM_BYTES>>>(qkv_p, brow_p, attn_p);
    gemm_wo_ln_kernel<<<512, 256>>>(attn_p, row_Wo, row_bo, pr, pnr_g, pnr_b, pr);

    // ---- stage 3: pr = LN(pr + tri_update_in(pr, single)) ----
    colsum_kernel<<<NSEQ, CDIM>>>(pr);
    trimix_ln_kernel<<<NROWS / 8, 256>>>(pr, pr, single, pnc_g, pnc_b, 1);

    // ---- stage 4: pr = LN(pr + col_attn(pr)) ----
    gemm_tf32_kernel<<<dim3(3, 512), 256>>>(pr, col_Wqkv, col_bqkv, qkv_p, NROWS, 384, 128, 0);
    attn_tile_kernel<<<dim3(4, NHEAD, NSEQ), 256, ATT_SMEM_BYTES>>>(qkv_p, bcol_p, attn_p);
    gemm_wo_ln_kernel<<<512, 256>>>(attn_p, col_Wo, col_bo, pr, pnc_g, pnc_b, pr);

    // ---- single-rep MLP + LN ----
    gemm128_kernel<<<dim3(2, 2), 256>>>(single, W1, b1, h1_p, NSEQ, 256, 128, 1);
    gemm128_kernel<<<dim3(1, 2), 256>>>(h1_p, W2, b2, h2_p, NSEQ, 128, 256, 1);
    residual_ln_kernel<<<NSEQ / 8, 256>>>(sr, single, h2_p, sn_g, sn_b, NSEQ);
}